// round 1
// baseline (speedup 1.0000x reference)
#include <cuda_runtime.h>

// ---------------------------------------------------------------------------
// ResidualBlock: x + BN2(capsconv2(BN1(capsconv1(x))))
// B=2, C=64, H=W=96, capsules 8x8, kernel 3x3 pad 1, routing iters = 3
// ---------------------------------------------------------------------------

static constexpr int Bv = 2;
static constexpr int Cv = 64;
static constexpr int Hv = 96;
static constexpr int Wv = 96;
static constexpr int Nv = Hv * Wv;          // 9216
static constexpr int OCn = 8;               // output capsule groups
static constexpr int Jn = 72;               // ic * kh * kw
static constexpr int WELEM = 8 * 72 * 64;   // 36864 floats per weight tensor

// scratch (device globals; no allocation allowed)
__device__ float g_xT[Bv * Nv * Cv];     // x in NHWC
__device__ float g_buf1[Bv * Nv * Cv];   // conv1 output, NHWC (pre-BN)
__device__ float g_buf2[Bv * Nv * Cv];   // conv2 output, NHWC (pre-BN)
__device__ float g_part[128 * 64 * 2];   // per-block partial (sum, sumsq)
__device__ float g_sb1[128];             // BN1: scale[0..63], bias[64..127]
__device__ float g_sb2[128];             // BN2: scale, bias

// ---------------------------------------------------------------------------
// NCHW -> NHWC transpose of x
// grid 288 (= 2 * 144), block 256
// ---------------------------------------------------------------------------
__global__ __launch_bounds__(256) void nchw_to_nhwc_kernel(const float* __restrict__ x) {
    __shared__ float tile[64][65];
    const int bb   = blockIdx.x / 144;
    const int t    = blockIdx.x % 144;
    const int base = t * 64;
    const int tid  = threadIdx.x;
#pragma unroll
    for (int it = 0; it < 16; ++it) {
        int idx = it * 256 + tid;
        int c = idx >> 6, s = idx & 63;
        tile[s][c] = x[(bb * 64 + c) * Nv + base + s];
    }
    __syncthreads();
#pragma unroll
    for (int it = 0; it < 16; ++it) {
        int idx = it * 256 + tid;
        int s = idx >> 6, c = idx & 63;
        g_xT[(bb * Nv + base + s) * 64 + c] = tile[s][c];
    }
}

// ---------------------------------------------------------------------------
// Fused capsule conv + dynamic routing.
//   FIRST=true : input g_xT (no BN), output g_buf1
//   FIRST=false: input g_buf1 with BN1 affine fused, output g_buf2
// grid (1152, 8): x -> (b, row, 16-wide column chunk); y -> output capsule o
// block 256 = 8 warps; warp w handles pixels (2w, 2w+1) of the 16.
// ---------------------------------------------------------------------------
template <bool FIRST>
__global__ __launch_bounds__(256) void conv_route_kernel(const float* __restrict__ wt) {
    // weights for this o, layout [l][j][m], per-l stride 584 floats (pad vs 576)
    __shared__ __align__(16) float sW[8 * 584];
    // input window: 3 rows x 18 cols x 64 ch (pad 68 to soften bank conflicts)
    __shared__ float sIn[3][18][68];

    const int o   = blockIdx.y;
    const int bx  = blockIdx.x;
    const int b   = bx / 576;
    const int r   = bx % 576;
    const int h   = r / 6;
    const int w0  = (r % 6) * 16;
    const int tid = threadIdx.x;

    const float* __restrict__ in = FIRST ? g_xT : g_buf1;
    float* __restrict__ outbuf   = FIRST ? g_buf1 : g_buf2;

    // --- load weights: src wt[o][j][l][m] -> sW[l*584 + j*8 + m]
    for (int s = tid; s < 4608; s += 256) {
        int j = s >> 6;
        int l = (s >> 3) & 7;
        int m = s & 7;
        sW[l * 584 + j * 8 + m] = wt[o * 4608 + s];
    }

    // --- load input window (zero pad outside), BN1 affine fused for layer 2
    for (int s = tid; s < 3 * 18 * 64; s += 256) {
        int c  = s & 63;
        int t  = s >> 6;
        int dw = t % 18;
        int dh = t / 18;
        int hh = h + dh - 1;
        int ww = w0 + dw - 1;
        float v = 0.f;
        if (hh >= 0 && hh < Hv && ww >= 0 && ww < Wv) {
            float u = in[(b * Nv + hh * Wv + ww) * 64 + c];
            v = FIRST ? u : fmaf(u, g_sb1[c], g_sb1[64 + c]);
        }
        sIn[dh][dw][c] = v;
    }
    __syncthreads();

    const int wid  = tid >> 5;
    const int lane = tid & 31;
    const int p0   = 2 * wid;  // first of two pixel columns this warp owns

    // priors[pos][jj][m]; lane owns j = lane + 32*jj (jj=2 active only lane<8)
    float pr[2][3][8];
#pragma unroll
    for (int a = 0; a < 2; ++a)
#pragma unroll
        for (int jj = 0; jj < 3; ++jj)
#pragma unroll
            for (int m = 0; m < 8; ++m) pr[a][jj][m] = 0.f;

#pragma unroll
    for (int jj = 0; jj < 3; ++jj) {
        int j = lane + 32 * jj;
        if (j > 71) j = 71;  // clamp; results masked later
        const int i   = j / 9;
        const int k   = j % 9;
        const int dh  = k / 3;
        const int dwk = k % 3;
#pragma unroll
        for (int l = 0; l < 8; ++l) {
            const float4* wp4 = reinterpret_cast<const float4*>(&sW[l * 584 + j * 8]);
            float4 wa = wp4[0];
            float4 wb = wp4[1];
            float wv[8] = {wa.x, wa.y, wa.z, wa.w, wb.x, wb.y, wb.z, wb.w};
            float a0 = sIn[dh][dwk + p0][i * 8 + l];
            float a1 = sIn[dh][dwk + p0 + 1][i * 8 + l];
#pragma unroll
            for (int m = 0; m < 8; ++m) {
                pr[0][jj][m] = fmaf(a0, wv[m], pr[0][jj][m]);
                pr[1][jj][m] = fmaf(a1, wv[m], pr[1][jj][m]);
            }
        }
    }

    const bool act2 = (lane < 8);

    // --- routing per pixel
#pragma unroll
    for (int p = 0; p < 2; ++p) {
        // |priors_j|^2 (constant across iterations)
        float n1v[3];
#pragma unroll
        for (int jj = 0; jj < 3; ++jj) {
            float s = 0.f;
#pragma unroll
            for (int m = 0; m < 8; ++m) s = fmaf(pr[p][jj][m], pr[p][jj][m], s);
            n1v[jj] = s;
        }

        // initial out = mean over all 72 j
        float outv[8];
#pragma unroll
        for (int m = 0; m < 8; ++m) {
            float s = pr[p][0][m] + pr[p][1][m] + (act2 ? pr[p][2][m] : 0.f);
#pragma unroll
            for (int off = 16; off > 0; off >>= 1)
                s += __shfl_xor_sync(0xffffffffu, s, off);
            outv[m] = s * (1.0f / 72.0f);
        }

#pragma unroll
        for (int it = 0; it < 3; ++it) {
            float n2 = 0.f;
#pragma unroll
            for (int m = 0; m < 8; ++m) n2 = fmaf(outv[m], outv[m], n2);

            float ev[3];
            float esum = 0.f;
#pragma unroll
            for (int jj = 0; jj < 3; ++jj) {
                float dot = 0.f;
#pragma unroll
                for (int m = 0; m < 8; ++m) dot = fmaf(pr[p][jj][m], outv[m], dot);
                float den   = fmaxf(n1v[jj] + n2 - dot, 1e-8f);
                float logit = __fdividef(dot, den);
                float e     = __expf(logit);
                bool  act   = (jj < 2) || act2;
                ev[jj]      = act ? e : 0.f;
                esum += ev[jj];
            }
#pragma unroll
            for (int off = 16; off > 0; off >>= 1)
                esum += __shfl_xor_sync(0xffffffffu, esum, off);
            float inv = __fdividef(1.0f, esum);

            float acc[8];
#pragma unroll
            for (int m = 0; m < 8; ++m) acc[m] = 0.f;
#pragma unroll
            for (int jj = 0; jj < 3; ++jj) {
                float pj = ev[jj] * inv;
#pragma unroll
                for (int m = 0; m < 8; ++m) acc[m] = fmaf(pj, pr[p][jj][m], acc[m]);
            }
#pragma unroll
            for (int m = 0; m < 8; ++m) {
                float s = acc[m];
#pragma unroll
                for (int off = 16; off > 0; off >>= 1)
                    s += __shfl_xor_sync(0xffffffffu, s, off);
                outv[m] = s;
            }
        }

        if (lane == 0) {
            int ww = w0 + p0 + p;
            float* dst = &outbuf[(b * Nv + h * Wv + ww) * 64 + o * 8];
            float4 v0 = make_float4(outv[0], outv[1], outv[2], outv[3]);
            float4 v1 = make_float4(outv[4], outv[5], outv[6], outv[7]);
            reinterpret_cast<float4*>(dst)[0] = v0;
            reinterpret_cast<float4*>(dst)[1] = v1;
        }
    }
}

// ---------------------------------------------------------------------------
// BN stats stage 1: per-block partial sum / sumsq per channel (deterministic).
// WHICH=1 reads g_buf1, WHICH=2 reads g_buf2. grid 128, block 512.
// ---------------------------------------------------------------------------
template <int WHICH>
__global__ __launch_bounds__(512) void bn_stats_kernel() {
    __shared__ float s1[512];
    __shared__ float s2[512];
    const float* __restrict__ buf = (WHICH == 1) ? g_buf1 : g_buf2;
    const int tid = threadIdx.x;
    const int base = blockIdx.x * 9216;
    float a = 0.f, q = 0.f;
#pragma unroll
    for (int it = 0; it < 18; ++it) {
        float v = buf[base + it * 512 + tid];
        a += v;
        q = fmaf(v, v, q);
    }
    s1[tid] = a;
    s2[tid] = q;
    __syncthreads();
    if (tid < 64) {
        float sa = 0.f, sq = 0.f;
#pragma unroll
        for (int r = 0; r < 8; ++r) {
            sa += s1[tid + r * 64];
            sq += s2[tid + r * 64];
        }
        g_part[(blockIdx.x * 64 + tid) * 2 + 0] = sa;
        g_part[(blockIdx.x * 64 + tid) * 2 + 1] = sq;
    }
}

// ---------------------------------------------------------------------------
// BN stats stage 2: mean/var -> per-channel affine (scale, bias). 1 block, 64 thr.
// ---------------------------------------------------------------------------
template <int WHICH>
__global__ __launch_bounds__(64) void bn_finalize_kernel(const float* __restrict__ gamma,
                                                         const float* __restrict__ beta) {
    const int c = threadIdx.x;
    float s = 0.f, q = 0.f;
    for (int kb = 0; kb < 128; ++kb) {
        s += g_part[(kb * 64 + c) * 2 + 0];
        q += g_part[(kb * 64 + c) * 2 + 1];
    }
    const float invM = 1.0f / (float)(Bv * Nv);
    float mean = s * invM;
    float var  = fmaf(-mean, mean, q * invM);
    float inv  = rsqrtf(var + 1e-5f);
    float scv  = gamma[c] * inv;
    float*  sb = (WHICH == 1) ? g_sb1 : g_sb2;
    sb[c]      = scv;
    sb[64 + c] = beta[c] - mean * scv;
}

// ---------------------------------------------------------------------------
// Final: out(NCHW) = x + BN2(g_buf2) with NHWC->NCHW transpose.
// grid 288, block 256.
// ---------------------------------------------------------------------------
__global__ __launch_bounds__(256) void final_kernel(const float* __restrict__ x,
                                                    float* __restrict__ out) {
    __shared__ float tile[64][65];
    const int bb   = blockIdx.x / 144;
    const int t    = blockIdx.x % 144;
    const int base = t * 64;
    const int tid  = threadIdx.x;
#pragma unroll
    for (int it = 0; it < 16; ++it) {
        int idx = it * 256 + tid;
        int s = idx >> 6, c = idx & 63;
        tile[s][c] = fmaf(g_buf2[(bb * Nv + base + s) * 64 + c], g_sb2[c], g_sb2[64 + c]);
    }
    __syncthreads();
#pragma unroll
    for (int it = 0; it < 16; ++it) {
        int idx = it * 256 + tid;
        int c = idx >> 6, s = idx & 63;
        int off = (bb * 64 + c) * Nv + base + s;
        out[off] = x[off] + tile[s][c];
    }
}

// ---------------------------------------------------------------------------
extern "C" void kernel_launch(void* const* d_in, const int* in_sizes, int n_in,
                              void* d_out, int out_size) {
    const float* x  = (const float*)d_in[0];
    const float* w1 = (const float*)d_in[1];
    const float* g1 = (const float*)d_in[2];
    const float* b1 = (const float*)d_in[3];
    const float* w2 = (const float*)d_in[4];
    const float* g2 = (const float*)d_in[5];
    const float* b2 = (const float*)d_in[6];
    float* out = (float*)d_out;

    nchw_to_nhwc_kernel<<<288, 256>>>(x);
    conv_route_kernel<true><<<dim3(1152, 8), 256>>>(w1);
    bn_stats_kernel<1><<<128, 512>>>();
    bn_finalize_kernel<1><<<1, 64>>>(g1, b1);
    conv_route_kernel<false><<<dim3(1152, 8), 256>>>(w2);
    bn_stats_kernel<2><<<128, 512>>>();
    bn_finalize_kernel<2><<<1, 64>>>(g2, b2);
    final_kernel<<<288, 256>>>(x, out);
}

// round 2
// speedup vs baseline: 1.0454x; 1.0454x over previous
#include <cuda_runtime.h>
#include <cooperative_groups.h>
#include <cooperative_groups/reduce.h>

namespace cg = cooperative_groups;

// ---------------------------------------------------------------------------
// ResidualBlock: x + BN2(capsconv2(BN1(capsconv1(x))))
// B=2, C=64, H=W=96, capsules 8x8, kernel 3x3 pad 1, routing iters = 3
// ---------------------------------------------------------------------------

static constexpr int Bv = 2;
static constexpr int Hv = 96;
static constexpr int Wv = 96;
static constexpr int Nv = Hv * Wv;  // 9216

typedef unsigned long long ull;

__device__ __forceinline__ ull pack2(float lo, float hi) {
    ull r; asm("mov.b64 %0,{%1,%2};" : "=l"(r) : "f"(lo), "f"(hi)); return r;
}
__device__ __forceinline__ void unpack2(ull v, float& lo, float& hi) {
    asm("mov.b64 {%0,%1},%2;" : "=f"(lo), "=f"(hi) : "l"(v));
}
__device__ __forceinline__ ull fma2(ull a, ull b, ull c) {
    ull d; asm("fma.rn.f32x2 %0,%1,%2,%3;" : "=l"(d) : "l"(a), "l"(b), "l"(c)); return d;
}
__device__ __forceinline__ ull mul2(ull a, ull b) {
    ull d; asm("mul.rn.f32x2 %0,%1,%2;" : "=l"(d) : "l"(a), "l"(b)); return d;
}
__device__ __forceinline__ ull add2(ull a, ull b) {
    ull d; asm("add.rn.f32x2 %0,%1,%2;" : "=l"(d) : "l"(a), "l"(b)); return d;
}

// scratch (device globals; no allocation allowed)
__device__ float g_xT[Bv * Nv * 64];     // x in NHWC
__device__ float g_buf1[Bv * Nv * 64];   // conv1 output, NHWC (pre-BN)
__device__ float g_buf2[Bv * Nv * 64];   // conv2 output, NHWC (pre-BN)
__device__ float g_part[128 * 64 * 2];   // per-block partial (sum, sumsq)
__device__ float g_sb1[128];             // BN1: scale[0..63], bias[64..127]
__device__ float g_sb2[128];             // BN2: scale, bias

// ---------------------------------------------------------------------------
// NCHW -> NHWC transpose of x. grid 288, block 256
// ---------------------------------------------------------------------------
__global__ __launch_bounds__(256) void nchw_to_nhwc_kernel(const float* __restrict__ x) {
    __shared__ float tile[64][65];
    const int bb   = blockIdx.x / 144;
    const int t    = blockIdx.x % 144;
    const int base = t * 64;
    const int tid  = threadIdx.x;
#pragma unroll
    for (int it = 0; it < 16; ++it) {
        int idx = it * 256 + tid;
        int c = idx >> 6, s = idx & 63;
        tile[s][c] = x[(bb * 64 + c) * Nv + base + s];
    }
    __syncthreads();
#pragma unroll
    for (int it = 0; it < 16; ++it) {
        int idx = it * 256 + tid;
        int s = idx >> 6, c = idx & 63;
        g_xT[(bb * Nv + base + s) * 64 + c] = tile[s][c];
    }
}

// ---------------------------------------------------------------------------
// Fused capsule conv + dynamic routing.
//   FIRST=true : input g_xT (no BN), output g_buf1
//   FIRST=false: input g_buf1 with BN1 affine fused, output g_buf2
// grid (192, 8): x -> (b, row); y -> output capsule o.
// block 256 = 8 warps; block loops over 6 chunks of 16 pixel columns;
// warp w handles pixels (2w, 2w+1) of each chunk.
// ---------------------------------------------------------------------------
template <bool FIRST>
__global__ __launch_bounds__(256, 2) void conv_route_kernel(const float* __restrict__ wt) {
    // weights for this o, layout [l][j][m], per-l stride 584 floats (pad vs 576)
    __shared__ __align__(16) float sW[8 * 584];
    // input window: 3 rows x 18 cols x 64 ch (pad 68)
    __shared__ __align__(16) float sIn[3][18][68];
    __shared__ float sSB[128];

    const int o   = blockIdx.y;
    const int b   = blockIdx.x / 96;
    const int h   = blockIdx.x % 96;
    const int tid = threadIdx.x;

    const float* __restrict__ in = FIRST ? g_xT : g_buf1;
    float* __restrict__ outbuf   = FIRST ? g_buf1 : g_buf2;

    if (!FIRST && tid < 128) sSB[tid] = g_sb1[tid];

    // weights: src wt[o][j][l][m] -> sW[l*584 + j*8 + m]
    for (int s = tid; s < 4608; s += 256) {
        int j = s >> 6;
        int l = (s >> 3) & 7;
        int m = s & 7;
        sW[l * 584 + j * 8 + m] = wt[o * 4608 + s];
    }

    const int wid  = tid >> 5;
    const int lane = tid & 31;
    const int p0   = 2 * wid;
    const bool act2 = (lane < 8);

    auto warp = cg::tiled_partition<32>(cg::this_thread_block());

    // decode j per jj once
    int ji[3], jdh[3], jdw[3], joff[3];
#pragma unroll
    for (int jj = 0; jj < 3; ++jj) {
        int j = lane + 32 * jj;
        if (j > 71) j = 71;
        ji[jj]   = j / 9;
        int k    = j % 9;
        jdh[jj]  = k / 3;
        jdw[jj]  = k % 3;
        joff[jj] = j * 8;
    }

    for (int cw = 0; cw < 6; ++cw) {
        const int w0 = cw * 16;
        __syncthreads();  // sW/sSB ready (cw==0) / prev chunk consumers done
        // load input window (zero pad), BN1 affine fused for layer 2
        for (int s = tid; s < 3 * 18 * 64; s += 256) {
            int c  = s & 63;
            int t  = s >> 6;
            int dw = t % 18;
            int dh = t / 18;
            int hh = h + dh - 1;
            int ww = w0 + dw - 1;
            float v = 0.f;
            if (hh >= 0 && hh < Hv && ww >= 0 && ww < Wv) {
                float u = in[(b * Nv + hh * Wv + ww) * 64 + c];
                v = FIRST ? u : fmaf(u, sSB[c], sSB[64 + c]);
            }
            sIn[dh][dw][c] = v;
        }
        __syncthreads();

        // ---- priors (packed f32x2): pr[pixel][jj][m-pair]
        ull pr[2][3][4];
#pragma unroll
        for (int a = 0; a < 2; ++a)
#pragma unroll
            for (int jj = 0; jj < 3; ++jj)
#pragma unroll
                for (int q = 0; q < 4; ++q) pr[a][jj][q] = 0ull;

#pragma unroll
        for (int jj = 0; jj < 3; ++jj) {
            const int i   = ji[jj];
            const int dh  = jdh[jj];
            const int dwk = jdw[jj];
            const ulonglong2* wrow =
                reinterpret_cast<const ulonglong2*>(&sW[joff[jj]]);
#pragma unroll
            for (int l = 0; l < 8; ++l) {
                ulonglong2 wa = wrow[l * (584 / 2) / 2];      // placeholder, fixed below
                (void)wa;
                const ulonglong2* wp =
                    reinterpret_cast<const ulonglong2*>(&sW[l * 584 + joff[jj]]);
                ulonglong2 w01 = wp[0];
                ulonglong2 w23 = wp[1];
                float a0 = sIn[dh][dwk + p0][i * 8 + l];
                float a1 = sIn[dh][dwk + p0 + 1][i * 8 + l];
                ull a0p = pack2(a0, a0);
                ull a1p = pack2(a1, a1);
                pr[0][jj][0] = fma2(a0p, w01.x, pr[0][jj][0]);
                pr[0][jj][1] = fma2(a0p, w01.y, pr[0][jj][1]);
                pr[0][jj][2] = fma2(a0p, w23.x, pr[0][jj][2]);
                pr[0][jj][3] = fma2(a0p, w23.y, pr[0][jj][3]);
                pr[1][jj][0] = fma2(a1p, w01.x, pr[1][jj][0]);
                pr[1][jj][1] = fma2(a1p, w01.y, pr[1][jj][1]);
                pr[1][jj][2] = fma2(a1p, w23.x, pr[1][jj][2]);
                pr[1][jj][3] = fma2(a1p, w23.y, pr[1][jj][3]);
            }
        }
        // zero inactive jj=2 slots (j>71)
        if (!act2) {
#pragma unroll
            for (int a = 0; a < 2; ++a)
#pragma unroll
                for (int q = 0; q < 4; ++q) pr[a][2][q] = 0ull;
        }

        // ---- routing per pixel
#pragma unroll
        for (int p = 0; p < 2; ++p) {
            // |priors_j|^2 (constant across iterations)
            float n1v[3];
#pragma unroll
            for (int jj = 0; jj < 3; ++jj) {
                ull t = mul2(pr[p][jj][0], pr[p][jj][0]);
                t = fma2(pr[p][jj][1], pr[p][jj][1], t);
                t = fma2(pr[p][jj][2], pr[p][jj][2], t);
                t = fma2(pr[p][jj][3], pr[p][jj][3], t);
                float lo, hi; unpack2(t, lo, hi);
                n1v[jj] = lo + hi;
            }

            // initial out = mean over 72 j
            float outs[8];
#pragma unroll
            for (int q = 0; q < 4; ++q) {
                ull s = add2(add2(pr[p][0][q], pr[p][1][q]), pr[p][2][q]);
                float lo, hi; unpack2(s, lo, hi);
                outs[2 * q]     = cg::reduce(warp, lo, cg::plus<float>()) * (1.0f / 72.0f);
                outs[2 * q + 1] = cg::reduce(warp, hi, cg::plus<float>()) * (1.0f / 72.0f);
            }

#pragma unroll
            for (int it = 0; it < 3; ++it) {
                ull op[4];
#pragma unroll
                for (int q = 0; q < 4; ++q) op[q] = pack2(outs[2 * q], outs[2 * q + 1]);

                ull t2 = mul2(op[0], op[0]);
                t2 = fma2(op[1], op[1], t2);
                t2 = fma2(op[2], op[2], t2);
                t2 = fma2(op[3], op[3], t2);
                float n2lo, n2hi; unpack2(t2, n2lo, n2hi);
                float n2 = n2lo + n2hi;

                float ev[3];
                float esum = 0.f;
#pragma unroll
                for (int jj = 0; jj < 3; ++jj) {
                    ull td = mul2(pr[p][jj][0], op[0]);
                    td = fma2(pr[p][jj][1], op[1], td);
                    td = fma2(pr[p][jj][2], op[2], td);
                    td = fma2(pr[p][jj][3], op[3], td);
                    float dlo, dhi; unpack2(td, dlo, dhi);
                    float dot = dlo + dhi;
                    float den   = fmaxf(n1v[jj] + n2 - dot, 1e-8f);
                    float logit = __fdividef(dot, den);
                    float e     = __expf(logit);
                    if (jj == 2 && !act2) e = 0.f;
                    ev[jj] = e;
                    esum += e;
                }
                esum = cg::reduce(warp, esum, cg::plus<float>());
                float inv = __fdividef(1.0f, esum);

                ull acc[4] = {0ull, 0ull, 0ull, 0ull};
#pragma unroll
                for (int jj = 0; jj < 3; ++jj) {
                    float pj = ev[jj] * inv;
                    ull pjp = pack2(pj, pj);
                    acc[0] = fma2(pjp, pr[p][jj][0], acc[0]);
                    acc[1] = fma2(pjp, pr[p][jj][1], acc[1]);
                    acc[2] = fma2(pjp, pr[p][jj][2], acc[2]);
                    acc[3] = fma2(pjp, pr[p][jj][3], acc[3]);
                }
#pragma unroll
                for (int q = 0; q < 4; ++q) {
                    float lo, hi; unpack2(acc[q], lo, hi);
                    outs[2 * q]     = cg::reduce(warp, lo, cg::plus<float>());
                    outs[2 * q + 1] = cg::reduce(warp, hi, cg::plus<float>());
                }
            }

            if (lane == 0) {
                int ww = w0 + p0 + p;
                float* dst = &outbuf[(b * Nv + h * Wv + ww) * 64 + o * 8];
                reinterpret_cast<float4*>(dst)[0] =
                    make_float4(outs[0], outs[1], outs[2], outs[3]);
                reinterpret_cast<float4*>(dst)[1] =
                    make_float4(outs[4], outs[5], outs[6], outs[7]);
            }
        }
    }
}

// ---------------------------------------------------------------------------
// BN stats stage 1: per-block partial sum / sumsq per channel (deterministic).
// grid 128, block 512.
// ---------------------------------------------------------------------------
template <int WHICH>
__global__ __launch_bounds__(512) void bn_stats_kernel() {
    __shared__ float s1[512];
    __shared__ float s2[512];
    const float* __restrict__ buf = (WHICH == 1) ? g_buf1 : g_buf2;
    const int tid = threadIdx.x;
    const int base = blockIdx.x * 9216;
    float a = 0.f, q = 0.f;
#pragma unroll
    for (int it = 0; it < 18; ++it) {
        float v = buf[base + it * 512 + tid];
        a += v;
        q = fmaf(v, v, q);
    }
    s1[tid] = a;
    s2[tid] = q;
    __syncthreads();
    if (tid < 64) {
        float sa = 0.f, sq = 0.f;
#pragma unroll
        for (int r = 0; r < 8; ++r) {
            sa += s1[tid + r * 64];
            sq += s2[tid + r * 64];
        }
        g_part[(blockIdx.x * 64 + tid) * 2 + 0] = sa;
        g_part[(blockIdx.x * 64 + tid) * 2 + 1] = sq;
    }
}

// ---------------------------------------------------------------------------
// BN stats stage 2: mean/var -> per-channel affine. 1 block, 512 threads.
// thread = c + 64*g; group g sums 16 of the 128 partials.
// ---------------------------------------------------------------------------
template <int WHICH>
__global__ __launch_bounds__(512) void bn_finalize_kernel(const float* __restrict__ gamma,
                                                          const float* __restrict__ beta) {
    __shared__ float r1[8][64];
    __shared__ float r2[8][64];
    const int tid = threadIdx.x;
    const int c = tid & 63;
    const int g = tid >> 6;
    float s = 0.f, q = 0.f;
#pragma unroll
    for (int u = 0; u < 16; ++u) {
        int kb = g * 16 + u;
        s += g_part[(kb * 64 + c) * 2 + 0];
        q += g_part[(kb * 64 + c) * 2 + 1];
    }
    r1[g][c] = s;
    r2[g][c] = q;
    __syncthreads();
    if (tid < 64) {
        float sa = 0.f, sq = 0.f;
#pragma unroll
        for (int r = 0; r < 8; ++r) { sa += r1[r][c]; sq += r2[r][c]; }
        const float invM = 1.0f / (float)(Bv * Nv);
        float mean = sa * invM;
        float var  = fmaf(-mean, mean, sq * invM);
        float inv  = rsqrtf(var + 1e-5f);
        float scv  = gamma[c] * inv;
        float* sb  = (WHICH == 1) ? g_sb1 : g_sb2;
        sb[c]      = scv;
        sb[64 + c] = beta[c] - mean * scv;
    }
}

// ---------------------------------------------------------------------------
// Final: out(NCHW) = x + BN2(g_buf2) with NHWC->NCHW transpose. grid 288.
// ---------------------------------------------------------------------------
__global__ __launch_bounds__(256) void final_kernel(const float* __restrict__ x,
                                                    float* __restrict__ out) {
    __shared__ float tile[64][65];
    const int bb   = blockIdx.x / 144;
    const int t    = blockIdx.x % 144;
    const int base = t * 64;
    const int tid  = threadIdx.x;
#pragma unroll
    for (int it = 0; it < 16; ++it) {
        int idx = it * 256 + tid;
        int s = idx >> 6, c = idx & 63;
        tile[s][c] = fmaf(g_buf2[(bb * Nv + base + s) * 64 + c], g_sb2[c], g_sb2[64 + c]);
    }
    __syncthreads();
#pragma unroll
    for (int it = 0; it < 16; ++it) {
        int idx = it * 256 + tid;
        int c = idx >> 6, s = idx & 63;
        int off = (bb * 64 + c) * Nv + base + s;
        out[off] = x[off] + tile[s][c];
    }
}

// ---------------------------------------------------------------------------
extern "C" void kernel_launch(void* const* d_in, const int* in_sizes, int n_in,
                              void* d_out, int out_size) {
    const float* x  = (const float*)d_in[0];
    const float* w1 = (const float*)d_in[1];
    const float* g1 = (const float*)d_in[2];
    const float* b1 = (const float*)d_in[3];
    const float* w2 = (const float*)d_in[4];
    const float* g2 = (const float*)d_in[5];
    const float* b2 = (const float*)d_in[6];
    float* out = (float*)d_out;

    nchw_to_nhwc_kernel<<<288, 256>>>(x);
    conv_route_kernel<true><<<dim3(192, 8), 256>>>(w1);
    bn_stats_kernel<1><<<128, 512>>>();
    bn_finalize_kernel<1><<<1, 512>>>(g1, b1);
    conv_route_kernel<false><<<dim3(192, 8), 256>>>(w2);
    bn_stats_kernel<2><<<128, 512>>>();
    bn_finalize_kernel<2><<<1, 512>>>(g2, b2);
    final_kernel<<<288, 256>>>(x, out);
}

// round 5
// speedup vs baseline: 2.1584x; 2.0646x over previous
#include <cuda_runtime.h>

// ---------------------------------------------------------------------------
// ResidualBlock: x + BN2(capsconv2(BN1(capsconv1(x))))
// B=2, C=64, H=W=96, capsules 8x8, kernel 3x3 pad 1, routing iters = 3
// ---------------------------------------------------------------------------

static constexpr int Bv = 2;
static constexpr int Hv = 96;
static constexpr int Wv = 96;
static constexpr int Nv = Hv * Wv;  // 9216

typedef unsigned long long ull;

__device__ __forceinline__ ull pack2(float lo, float hi) {
    ull r; asm("mov.b64 %0,{%1,%2};" : "=l"(r) : "f"(lo), "f"(hi)); return r;
}
__device__ __forceinline__ void unpack2(ull v, float& lo, float& hi) {
    asm("mov.b64 {%0,%1},%2;" : "=f"(lo), "=f"(hi) : "l"(v));
}
__device__ __forceinline__ ull fma2(ull a, ull b, ull c) {
    ull d; asm("fma.rn.f32x2 %0,%1,%2,%3;" : "=l"(d) : "l"(a), "l"(b), "l"(c)); return d;
}
__device__ __forceinline__ ull mul2(ull a, ull b) {
    ull d; asm("mul.rn.f32x2 %0,%1,%2;" : "=l"(d) : "l"(a), "l"(b)); return d;
}
__device__ __forceinline__ ull add2(ull a, ull b) {
    ull d; asm("add.rn.f32x2 %0,%1,%2;" : "=l"(d) : "l"(a), "l"(b)); return d;
}
__device__ __forceinline__ ull shfl_xor2(ull v, int m) {
    float lo, hi; unpack2(v, lo, hi);
    lo = __shfl_xor_sync(0xffffffffu, lo, m);
    hi = __shfl_xor_sync(0xffffffffu, hi, m);
    return pack2(lo, hi);
}

// scratch (device globals; no allocation allowed)
__device__ float g_xT[Bv * Nv * 64];     // x in NHWC
__device__ float g_buf1[Bv * Nv * 64];   // conv1 output, NHWC (pre-BN)
__device__ float g_buf2[Bv * Nv * 64];   // conv2 output, NHWC (pre-BN)
__device__ float g_part[64 * 64 * 2];    // per-block partial (sum, sumsq)
__device__ float g_sb1[128];             // BN1: scale[0..63], bias[64..127]
__device__ float g_sb2[128];             // BN2: scale, bias
__device__ float g_w2p[8 * 4608];        // w2 with BN1 scale folded
__device__ float g_bias2[8 * 576];       // per (o,j,m) bias from BN1 shift

// ---------------------------------------------------------------------------
// NCHW -> NHWC transpose of x. grid 288, block 256
// ---------------------------------------------------------------------------
__global__ __launch_bounds__(256) void nchw_to_nhwc_kernel(const float* __restrict__ x) {
    __shared__ float tile[64][65];
    const int bb   = blockIdx.x / 144;
    const int t    = blockIdx.x % 144;
    const int base = t * 64;
    const int tid  = threadIdx.x;
#pragma unroll
    for (int it = 0; it < 16; ++it) {
        int idx = it * 256 + tid;
        int c = idx >> 6, s = idx & 63;
        tile[s][c] = x[(bb * 64 + c) * Nv + base + s];
    }
    __syncthreads();
#pragma unroll
    for (int it = 0; it < 16; ++it) {
        int idx = it * 256 + tid;
        int s = idx >> 6, c = idx & 63;
        g_xT[(bb * Nv + base + s) * 64 + c] = tile[s][c];
    }
}

// ---------------------------------------------------------------------------
// Fold BN1 affine into conv2 weights + bias.  grid 144, block 256.
//   g_w2p[o,j,l,m]  = w2[o,j,l,m] * sb1_scale[i*8+l]     (i = j/9)
//   g_bias2[o,j,m]  = sum_l sb1_bias[i*8+l] * w2[o,j,l,m]
// ---------------------------------------------------------------------------
__global__ __launch_bounds__(256) void wprep_kernel(const float* __restrict__ w2) {
    int idx = blockIdx.x * 256 + threadIdx.x;
    if (idx < 36864) {
        int i = (idx / 576) & 7;
        int l = (idx >> 3) & 7;
        g_w2p[idx] = w2[idx] * g_sb1[i * 8 + l];
    }
    if (idx < 4608) {
        int o  = idx / 576;
        int jm = idx % 576;
        int j  = jm >> 3;
        int m  = jm & 7;
        int i  = j / 9;
        float s = 0.f;
#pragma unroll
        for (int l = 0; l < 8; ++l)
            s = fmaf(g_sb1[64 + i * 8 + l], w2[o * 4608 + j * 64 + l * 8 + m], s);
        g_bias2[idx] = s;
    }
}

// ---------------------------------------------------------------------------
// Fused capsule conv + dynamic routing.
// grid (192, 8): x -> (b, row h); y -> output capsule o. block = 128 (4 warps).
// 6 chunks of 16 pixel columns; warp handles 4 pixels; lane = q*8+g where
// q = pixel quarter, g = input capsule i. Lane owns j = g*9 + k (k=0..8), all m.
// cp.async double-buffered input window. BN1 folded into conv2 weights/bias,
// bias masked by patch validity (reference zero-pads the post-BN input).
// ---------------------------------------------------------------------------
static constexpr int WSTR = 580;          // per-l weight stride (words)
static constexpr int WINW = 3 * 18 * 64;  // window floats = 3456

template <bool FIRST>
__global__ __launch_bounds__(128, 4) void conv_route_kernel(const float* __restrict__ wt) {
    __shared__ __align__(16) float sW[8 * WSTR];     // 18560 B
    __shared__ __align__(16) float sWin[2][WINW];    // 27648 B
    __shared__ __align__(16) float sB[576];          //  2304 B

    const int o   = blockIdx.y;
    const int b   = blockIdx.x / 96;
    const int h   = blockIdx.x % 96;
    const int tid = threadIdx.x;

    const float* __restrict__ in   = FIRST ? g_xT : g_buf1;
    const float* __restrict__ wsrc = FIRST ? wt : (const float*)g_w2p;
    float* __restrict__ outbuf     = FIRST ? g_buf1 : g_buf2;

    // ---- cp.async window loader (zero-fill OOB) ----
    auto issue_chunk = [&](int cw, int buf) {
        const int w0 = cw * 16;
        float* dst = sWin[buf];
#pragma unroll
        for (int it = 0; it < 7; ++it) {
            int f4 = it * 128 + tid;
            if (f4 < 864) {
                int cg = (f4 & 15) * 4;            // channel group start
                int t  = f4 >> 4;                  // dh*18+dw, 0..53
                int dh = t / 18, dw = t % 18;
                int hh = h + dh - 1;
                int ww = w0 + dw - 1;
                bool ok = (hh >= 0) && (hh < Hv) && (ww >= 0) && (ww < Wv);
                const float* src = ok ? &in[((size_t)(b * Nv + hh * Wv + ww)) * 64 + cg] : in;
                int csw = cg ^ ((cg & 32) >> 3);   // XOR-4 swizzle on upper half
                unsigned sa = (unsigned)__cvta_generic_to_shared(&dst[t * 64 + csw]);
                int sz = ok ? 16 : 0;
                asm volatile("cp.async.cg.shared.global [%0], [%1], 16, %2;\n"
                             :: "r"(sa), "l"(src), "r"(sz) : "memory");
            }
        }
        asm volatile("cp.async.commit_group;\n" ::: "memory");
    };

    issue_chunk(0, 0);

    // ---- weights: wsrc[o*4608 + j*64 + l*8 + m] -> sW[l*WSTR + j*8 + 4*(j/36) + m]
    for (int s = tid; s < 4608; s += 128) {
        int j = s >> 6;
        int l = (s >> 3) & 7;
        int m = s & 7;
        sW[l * WSTR + j * 8 + 4 * (j / 36) + m] = wsrc[o * 4608 + s];
    }
    // ---- bias (layer 2 only)
    if (!FIRST) {
        for (int s = tid; s < 576; s += 128) sB[s] = g_bias2[o * 576 + s];
    }

    asm volatile("cp.async.wait_group 0;\n" ::: "memory");
    __syncthreads();

    const int wid  = tid >> 5;
    const int lane = tid & 31;
    const int q    = lane >> 3;   // pixel quarter
    const int g    = lane & 7;    // input capsule i
    const int p    = wid * 4 + q; // pixel col within chunk (0..15)

    // lane-constant swizzled channel offsets for a-loads
    const int cz0 = (g * 8)     ^ (((g * 8)     & 32) >> 3);
    const int cz1 = (g * 8 + 4) ^ (((g * 8 + 4) & 32) >> 3);
    const int jo  = 72 * g + 4 * (g >> 2);  // swizzled weight base (k=0)

    // per-k row validity (h direction) — constant over chunks
    bool hvalid[3];
#pragma unroll
    for (int dh = 0; dh < 3; ++dh) {
        int hh = h + dh - 1;
        hvalid[dh] = (hh >= 0) && (hh < Hv);
    }

    for (int cw = 0; cw < 6; ++cw) {
        const int cur = cw & 1;
        if (cw < 5) issue_chunk(cw + 1, cur ^ 1);

        const float* win = sWin[cur];
        const int ww0 = cw * 16 + p - 1;  // leftmost patch column for this pixel

        // ---- priors pr[k][mpair], init = bias (masked by patch validity) or 0
        ull pr[9][4];
        if (FIRST) {
#pragma unroll
            for (int k = 0; k < 9; ++k)
#pragma unroll
                for (int mq = 0; mq < 4; ++mq) pr[k][mq] = 0ull;
        } else {
#pragma unroll
            for (int k = 0; k < 9; ++k) {
                int dh = k / 3, dw = k % 3;
                bool v = hvalid[dh] && ((unsigned)(ww0 + dw) < (unsigned)Wv);
                if (v) {
                    const ulonglong2* bj =
                        reinterpret_cast<const ulonglong2*>(&sB[(g * 9 + k) * 8]);
                    ulonglong2 b0 = bj[0];
                    ulonglong2 b1 = bj[1];
                    pr[k][0] = b0.x; pr[k][1] = b0.y;
                    pr[k][2] = b1.x; pr[k][3] = b1.y;
                } else {
#pragma unroll
                    for (int mq = 0; mq < 4; ++mq) pr[k][mq] = 0ull;
                }
            }
        }

#pragma unroll
        for (int k = 0; k < 9; ++k) {
            const int dh = k / 3, dw = k % 3;
            const float* arow = &win[(dh * 18 + p + dw) * 64];
            float4 aA = *reinterpret_cast<const float4*>(&arow[cz0]);
            float4 aB = *reinterpret_cast<const float4*>(&arow[cz1]);
            float av[8] = {aA.x, aA.y, aA.z, aA.w, aB.x, aB.y, aB.z, aB.w};
#pragma unroll
            for (int l = 0; l < 8; ++l) {
                const ulonglong2* wp =
                    reinterpret_cast<const ulonglong2*>(&sW[l * WSTR + jo + 8 * k]);
                ulonglong2 w01 = wp[0];
                ulonglong2 w23 = wp[1];
                ull ap = pack2(av[l], av[l]);
                pr[k][0] = fma2(ap, w01.x, pr[k][0]);
                pr[k][1] = fma2(ap, w01.y, pr[k][1]);
                pr[k][2] = fma2(ap, w23.x, pr[k][2]);
                pr[k][3] = fma2(ap, w23.y, pr[k][3]);
            }
        }

        // ---- n1[k] = |pr_k|^2 (in-lane)
        float n1[9];
#pragma unroll
        for (int k = 0; k < 9; ++k) {
            ull t = mul2(pr[k][0], pr[k][0]);
            t = fma2(pr[k][1], pr[k][1], t);
            t = fma2(pr[k][2], pr[k][2], t);
            t = fma2(pr[k][3], pr[k][3], t);
            float lo, hi; unpack2(t, lo, hi);
            n1[k] = lo + hi;
        }

        // ---- initial out = mean over 72 j (in-lane 9-sum + 3-level butterfly)
        ull outv[4];
#pragma unroll
        for (int mq = 0; mq < 4; ++mq) {
            ull s = pr[0][mq];
#pragma unroll
            for (int k = 1; k < 9; ++k) s = add2(pr[k][mq], s);
#pragma unroll
            for (int off = 1; off < 8; off <<= 1) s = add2(s, shfl_xor2(s, off));
            outv[mq] = mul2(s, pack2(1.0f / 72.0f, 1.0f / 72.0f));
        }

        // ---- 3 routing iterations
#pragma unroll
        for (int it = 0; it < 3; ++it) {
            ull t2 = mul2(outv[0], outv[0]);
            t2 = fma2(outv[1], outv[1], t2);
            t2 = fma2(outv[2], outv[2], t2);
            t2 = fma2(outv[3], outv[3], t2);
            float n2lo, n2hi; unpack2(t2, n2lo, n2hi);
            float n2 = n2lo + n2hi;

            float ev[9];
            float esum = 0.f;
#pragma unroll
            for (int k = 0; k < 9; ++k) {
                ull td = mul2(pr[k][0], outv[0]);
                td = fma2(pr[k][1], outv[1], td);
                td = fma2(pr[k][2], outv[2], td);
                td = fma2(pr[k][3], outv[3], td);
                float dlo, dhi; unpack2(td, dlo, dhi);
                float dot = dlo + dhi;
                float den = fmaxf(n1[k] + n2 - dot, 1e-8f);
                float e   = __expf(__fdividef(dot, den));
                ev[k] = e;
                esum += e;
            }
#pragma unroll
            for (int off = 1; off < 8; off <<= 1)
                esum += __shfl_xor_sync(0xffffffffu, esum, off);
            float inv = __fdividef(1.0f, esum);

            ull acc[4] = {0ull, 0ull, 0ull, 0ull};
#pragma unroll
            for (int k = 0; k < 9; ++k) {
                float pj = ev[k] * inv;
                ull pjp = pack2(pj, pj);
                acc[0] = fma2(pjp, pr[k][0], acc[0]);
                acc[1] = fma2(pjp, pr[k][1], acc[1]);
                acc[2] = fma2(pjp, pr[k][2], acc[2]);
                acc[3] = fma2(pjp, pr[k][3], acc[3]);
            }
#pragma unroll
            for (int mq = 0; mq < 4; ++mq) {
#pragma unroll
                for (int off = 1; off < 8; off <<= 1)
                    acc[mq] = add2(acc[mq], shfl_xor2(acc[mq], off));
                outv[mq] = acc[mq];
            }
        }

        if (g == 0) {
            float o0, o1, o2, o3, o4, o5, o6, o7;
            unpack2(outv[0], o0, o1);
            unpack2(outv[1], o2, o3);
            unpack2(outv[2], o4, o5);
            unpack2(outv[3], o6, o7);
            int ww = cw * 16 + p;
            float* dst = &outbuf[((size_t)(b * Nv + h * Wv + ww)) * 64 + o * 8];
            reinterpret_cast<float4*>(dst)[0] = make_float4(o0, o1, o2, o3);
            reinterpret_cast<float4*>(dst)[1] = make_float4(o4, o5, o6, o7);
        }

        if (cw < 5) {
            asm volatile("cp.async.wait_group 0;\n" ::: "memory");
            __syncthreads();
        }
    }
}

// ---------------------------------------------------------------------------
// BN stats stage 1: per-block partial sum / sumsq per channel. grid 64, block 512.
// ---------------------------------------------------------------------------
template <int WHICH>
__global__ __launch_bounds__(512) void bn_stats_kernel() {
    __shared__ float s1[512];
    __shared__ float s2[512];
    const float* __restrict__ buf = (WHICH == 1) ? g_buf1 : g_buf2;
    const int tid = threadIdx.x;
    const int base = blockIdx.x * 18432;
    float a = 0.f, q = 0.f;
#pragma unroll
    for (int it = 0; it < 36; ++it) {
        float v = buf[base + it * 512 + tid];
        a += v;
        q = fmaf(v, v, q);
    }
    s1[tid] = a;
    s2[tid] = q;
    __syncthreads();
    if (tid < 64) {
        float sa = 0.f, sq = 0.f;
#pragma unroll
        for (int r = 0; r < 8; ++r) {
            sa += s1[tid + r * 64];
            sq += s2[tid + r * 64];
        }
        g_part[(blockIdx.x * 64 + tid) * 2 + 0] = sa;
        g_part[(blockIdx.x * 64 + tid) * 2 + 1] = sq;
    }
}

// ---------------------------------------------------------------------------
// BN stats stage 2: mean/var -> per-channel affine. 1 block, 512 threads.
// ---------------------------------------------------------------------------
template <int WHICH>
__global__ __launch_bounds__(512) void bn_finalize_kernel(const float* __restrict__ gamma,
                                                          const float* __restrict__ beta) {
    __shared__ float r1[8][64];
    __shared__ float r2[8][64];
    const int tid = threadIdx.x;
    const int c = tid & 63;
    const int g = tid >> 6;
    float s = 0.f, q = 0.f;
#pragma unroll
    for (int u = 0; u < 8; ++u) {
        int kb = g * 8 + u;
        s += g_part[(kb * 64 + c) * 2 + 0];
        q += g_part[(kb * 64 + c) * 2 + 1];
    }
    r1[g][c] = s;
    r2[g][c] = q;
    __syncthreads();
    if (tid < 64) {
        float sa = 0.f, sq = 0.f;
#pragma unroll
        for (int r = 0; r < 8; ++r) { sa += r1[r][c]; sq += r2[r][c]; }
        const float invM = 1.0f / (float)(Bv * Nv);
        float mean = sa * invM;
        float var  = fmaf(-mean, mean, sq * invM);
        float inv  = rsqrtf(var + 1e-5f);
        float scv  = gamma[c] * inv;
        float* sb  = (WHICH == 1) ? g_sb1 : g_sb2;
        sb[c]      = scv;
        sb[64 + c] = beta[c] - mean * scv;
    }
}

// ---------------------------------------------------------------------------
// Final: out(NCHW) = x + BN2(g_buf2) with NHWC->NCHW transpose. grid 288.
// ---------------------------------------------------------------------------
__global__ __launch_bounds__(256) void final_kernel(const float* __restrict__ x,
                                                    float* __restrict__ out) {
    __shared__ float tile[64][65];
    const int bb   = blockIdx.x / 144;
    const int t    = blockIdx.x % 144;
    const int base = t * 64;
    const int tid  = threadIdx.x;
#pragma unroll
    for (int it = 0; it < 16; ++it) {
        int idx = it * 256 + tid;
        int s = idx >> 6, c = idx & 63;
        tile[s][c] = fmaf(g_buf2[(bb * Nv + base + s) * 64 + c], g_sb2[c], g_sb2[64 + c]);
    }
    __syncthreads();
#pragma unroll
    for (int it = 0; it < 16; ++it) {
        int idx = it * 256 + tid;
        int c = idx >> 6, s = idx & 63;
        int off = (bb * 64 + c) * Nv + base + s;
        out[off] = x[off] + tile[s][c];
    }
}

// ---------------------------------------------------------------------------
extern "C" void kernel_launch(void* const* d_in, const int* in_sizes, int n_in,
                              void* d_out, int out_size) {
    const float* x  = (const float*)d_in[0];
    const float* w1 = (const float*)d_in[1];
    const float* g1 = (const float*)d_in[2];
    const float* b1 = (const float*)d_in[3];
    const float* w2 = (const float*)d_in[4];
    const float* g2 = (const float*)d_in[5];
    const float* b2 = (const float*)d_in[6];
    float* out = (float*)d_out;

    nchw_to_nhwc_kernel<<<288, 256>>>(x);
    conv_route_kernel<true><<<dim3(192, 8), 128>>>(w1);
    bn_stats_kernel<1><<<64, 512>>>();
    bn_finalize_kernel<1><<<1, 512>>>(g1, b1);
    wprep_kernel<<<144, 256>>>(w2);
    conv_route_kernel<false><<<dim3(192, 8), 128>>>(w2);  // kernel uses g_w2p internally
    bn_stats_kernel<2><<<64, 512>>>();
    bn_finalize_kernel<2><<<1, 512>>>(g2, b2);
    final_kernel<<<288, 256>>>(x, out);
}